// round 5
// baseline (speedup 1.0000x reference)
#include <cuda_runtime.h>
#include <cstdint>

namespace {

constexpr int B_  = 32768;
constexpr int A_  = 32;
constexpr int D_  = 64;    // pred dim
constexpr int H_  = 128;   // hidden dim
constexpr int K_  = 128;   // 2*D context width
constexpr int TB  = 128;   // batch rows per block
constexpr int NT  = 512;   // threads per block (16 warps x 8 rows)
constexpr int RW  = 8;     // rows per warp

// smem float offsets
constexpr int OFF_CTX   = 0;                  // [128][128] f
constexpr int OFF_HCTX  = 16384;              // [128][128] f
constexpr int OFF_PREDS = 32768;              // [128][64]  f
constexpr int OFF_WKP   = 40960;              // u64 [64 kp][64 d]  (4096 u64)
constexpr int OFF_WPH   = 49152;              // u64 [32 dp][stride 130][h] (4160 u64)
constexpr int SMEM_F    = 57472;              // total floats
constexpr int SMEM_BYTES = SMEM_F * 4;        // 229888 B

// wc overlay (prologue only): u64 [64 kp][stride 130], base at OFF_PREDS
constexpr int WPH_STRIDE = 130;
constexpr int WC_STRIDE  = 130;

using u64 = unsigned long long;

__device__ __forceinline__ void ffma2(u64& d, u64 a, u64 b) {
  asm("fma.rn.f32x2 %0, %1, %2, %0;" : "+l"(d) : "l"(a), "l"(b));
}
__device__ __forceinline__ u64 pack2(float a, float b) {
  u64 r;
  asm("mov.b64 %0, {%1, %2};" : "=l"(r) : "f"(a), "f"(b));
  return r;
}
__device__ __forceinline__ void unpack2(u64 v, float& lo, float& hi) {
  asm("mov.b64 {%0, %1}, %2;" : "=f"(lo), "=f"(hi) : "l"(v));
}

}  // namespace

// __device__ scratch (no runtime alloc allowed)
__device__ u64   g_wkp [A_ * (K_ / 2) * D_];   // [a][kp][d] : (Weff[2kp][d], Weff[2kp+1][d])
__device__ float g_beff[A_ * D_];              // [a][d]

// ---------------------------------------------------------------------------
// Precompute: Weff[a] = W2[a] @ W1[a] (K x D, stored kp-packed u64),
//             beff[a][d] = W2[a][d,:] . b1[a] + b2[a][d]
// ---------------------------------------------------------------------------
__global__ void __launch_bounds__(256)
cmb_precompute_kernel(const float* __restrict__ W1, const float* __restrict__ b1,
                      const float* __restrict__ W2, const float* __restrict__ b2) {
  __shared__ float w1s[H_][K_];
  __shared__ float w2s[D_][H_];
  const int a   = blockIdx.x;
  const int tid = threadIdx.x;
  const float* W1a = W1 + (size_t)a * H_ * K_;
  const float* W2a = W2 + (size_t)a * D_ * H_;

  for (int i = tid; i < H_ * K_ / 4; i += 256)
    reinterpret_cast<float4*>(&w1s[0][0])[i] =
        reinterpret_cast<const float4*>(W1a)[i];
  for (int i = tid; i < D_ * H_ / 4; i += 256)
    reinterpret_cast<float4*>(&w2s[0][0])[i] =
        reinterpret_cast<const float4*>(W2a)[i];
  __syncthreads();

  const int kq = tid & 31;   // k0 = 4*kq
  const int dt = tid >> 5;   // d0 = 8*dt
  const int k0 = kq * 4, d0 = dt * 8;

  float acc[4][8];
#pragma unroll
  for (int i = 0; i < 4; i++)
#pragma unroll
    for (int j = 0; j < 8; j++) acc[i][j] = 0.f;

  for (int h = 0; h < H_; h++) {
    float4 w1v = *reinterpret_cast<const float4*>(&w1s[h][k0]);
    float w1x[4] = {w1v.x, w1v.y, w1v.z, w1v.w};
#pragma unroll
    for (int j = 0; j < 8; j++) {
      float w2v = w2s[d0 + j][h];
#pragma unroll
      for (int i = 0; i < 4; i++) acc[i][j] = fmaf(w2v, w1x[i], acc[i][j]);
    }
  }

  // packed store: (k even, k odd) pairs
  u64* dst = g_wkp + (size_t)a * (K_ / 2) * D_;
  const int kp0 = k0 >> 1;
#pragma unroll
  for (int j = 0; j < 8; j++) {
    dst[(kp0 + 0) * D_ + d0 + j] = pack2(acc[0][j], acc[1][j]);
    dst[(kp0 + 1) * D_ + d0 + j] = pack2(acc[2][j], acc[3][j]);
  }

  if (tid < D_) {
    float s = b2[a * D_ + tid];
    for (int h = 0; h < H_; h++) s = fmaf(w2s[tid][h], b1[a * H_ + h], s);
    g_beff[a * D_ + tid] = s;
  }
}

// ---------------------------------------------------------------------------
// Main fused kernel: warp-per-8-rows, k-pair-packed FFMA2
// ---------------------------------------------------------------------------
__global__ void __launch_bounds__(NT, 1)
cmb_fused_kernel(const int* __restrict__ x, const int* __restrict__ y,
                 const float* __restrict__ cemb, const float* __restrict__ wemb,
                 const float* __restrict__ Wr1, const float* __restrict__ br1,
                 const float* __restrict__ Wr2,
                 float* __restrict__ out) {
  extern __shared__ float smf[];
  u64* WKP = reinterpret_cast<u64*>(smf + OFF_WKP);
  u64* WPH = reinterpret_cast<u64*>(smf + OFF_WPH);
  u64* WC  = reinterpret_cast<u64*>(smf + OFF_PREDS);   // prologue overlay

  const int tid = threadIdx.x;
  const int b0g = blockIdx.x * TB;
  const int wid = tid >> 5;
  const int lid = tid & 31;
  const int r0  = wid * RW;       // warp's first row (0..120)
  const int dl  = 2 * lid;        // lane's d/h base

  // ---- Phase A: ctx gather, wemb copy, wc staging (all independent) ----
  {
    int b = tid >> 2, part = tid & 3;
    int gb = b0g + b;
    int x0 = x[gb * 2 + 0];
    int x1 = x[gb * 2 + 1];
#pragma unroll
    for (int q = 0; q < 8; q++) {
      int k = part * 32 + q * 4;
      const float* src = (k < 64) ? (cemb + (size_t)x0 * 64 + k)
                                  : (cemb + (size_t)x1 * 64 + (k - 64));
      *reinterpret_cast<float4*>(&smf[OFF_CTX + b * K_ + k]) =
          *reinterpret_cast<const float4*>(src);
    }
    int yy = y[gb];
#pragma unroll
    for (int q = 0; q < 4; q++) {
      int d = part * 16 + q * 4;
      *reinterpret_cast<float4*>(&out[(size_t)B_ * 64 + (size_t)gb * 64 + d]) =
          *reinterpret_cast<const float4*>(wemb + (size_t)yy * 64 + d);
    }
  }
  // wc[kp][h] = (Wr1[h][2kp], Wr1[h][2kp+1]) ; idx = h*64 + kp (coalesced src)
  for (int i = tid; i < 64 * H_; i += NT) {
    int h = i >> 6, kp = i & 63;
    WC[kp * WC_STRIDE + h] =
        *reinterpret_cast<const u64*>(&Wr1[h * 192 + 2 * kp]);
  }
  __syncthreads();

  // ---- hctx = ctx @ Wc^T + br1  (per-warp rows, lane covers 2 h x 2 passes)
  float wr2v[2][2];
#pragma unroll
  for (int p = 0; p < 2; p++) {
    const int h0 = p * 64 + dl;
    wr2v[p][0] = Wr2[h0];
    wr2v[p][1] = Wr2[h0 + 1];

    u64 acc2[RW][2];
#pragma unroll
    for (int r = 0; r < RW; r++) { acc2[r][0] = 0ull; acc2[r][1] = 0ull; }

    for (int kb = 0; kb < K_; kb += 4) {
      const int kp = kb >> 1;
      ulonglong2 w0 = *reinterpret_cast<const ulonglong2*>(&WC[(kp + 0) * WC_STRIDE + h0]);
      ulonglong2 w1 = *reinterpret_cast<const ulonglong2*>(&WC[(kp + 1) * WC_STRIDE + h0]);
#pragma unroll
      for (int r = 0; r < RW; r++) {
        ulonglong2 x2 = *reinterpret_cast<const ulonglong2*>(&smf[OFF_CTX + (r0 + r) * K_ + kb]);
        ffma2(acc2[r][0], x2.x, w0.x);
        ffma2(acc2[r][1], x2.x, w0.y);
        ffma2(acc2[r][0], x2.y, w1.x);
        ffma2(acc2[r][1], x2.y, w1.y);
      }
    }
    float bias0 = br1[h0], bias1 = br1[h0 + 1];
#pragma unroll
    for (int r = 0; r < RW; r++) {
      float e0, o0, e1, o1;
      unpack2(acc2[r][0], e0, o0);
      unpack2(acc2[r][1], e1, o1);
      *reinterpret_cast<u64*>(&smf[OFF_HCTX + (r0 + r) * H_ + h0]) =
          pack2(e0 + o0 + bias0, e1 + o1 + bias1);
    }
  }
  __syncthreads();   // wc fully consumed

  // ---- stage wph[dp][h] = (Wr1[h][128+2dp], Wr1[h][128+2dp+1]) ----
  for (int i = tid; i < 32 * H_; i += NT) {
    int h = i >> 5, dp = i & 31;
    WPH[dp * WPH_STRIDE + h] =
        *reinterpret_cast<const u64*>(&Wr1[h * 192 + 128 + 2 * dp]);
  }

  float bestr[RW];
#pragma unroll
  for (int r = 0; r < RW; r++) bestr[r] = 3.0e38f;

  // ---- Action loop ----
  for (int a = 0; a < A_; a++) {
    __syncthreads();   // prev action done everywhere; (a==0: wph staged)

    // stage WKP[a] (straight u64 copy, preformatted)
    {
      const ulonglong2* src = reinterpret_cast<const ulonglong2*>(g_wkp + (size_t)a * 64 * D_);
      ulonglong2* dst = reinterpret_cast<ulonglong2*>(WKP);
      for (int i = tid; i < 64 * D_ / 2; i += NT) dst[i] = src[i];
    }
    float bf0, bf1;
    unpack2(*reinterpret_cast<const u64*>(&g_beff[a * D_ + dl]), bf0, bf1);
    __syncthreads();

    // GEMM1: preds = ctx @ Weff (+beff).  lane: d = {dl, dl+1}
    {
      u64 acc2[RW][2];
#pragma unroll
      for (int r = 0; r < RW; r++) { acc2[r][0] = 0ull; acc2[r][1] = 0ull; }

      for (int kb = 0; kb < K_; kb += 4) {
        const int kp = kb >> 1;
        ulonglong2 w0 = *reinterpret_cast<const ulonglong2*>(&WKP[(kp + 0) * D_ + dl]);
        ulonglong2 w1 = *reinterpret_cast<const ulonglong2*>(&WKP[(kp + 1) * D_ + dl]);
#pragma unroll
        for (int r = 0; r < RW; r++) {
          ulonglong2 x2 = *reinterpret_cast<const ulonglong2*>(&smf[OFF_CTX + (r0 + r) * K_ + kb]);
          ffma2(acc2[r][0], x2.x, w0.x);
          ffma2(acc2[r][1], x2.x, w0.y);
          ffma2(acc2[r][0], x2.y, w1.x);
          ffma2(acc2[r][1], x2.y, w1.y);
        }
      }
#pragma unroll
      for (int r = 0; r < RW; r++) {
        float e0, o0, e1, o1;
        unpack2(acc2[r][0], e0, o0);
        unpack2(acc2[r][1], e1, o1);
        *reinterpret_cast<u64*>(&smf[OFF_PREDS + (r0 + r) * D_ + dl]) =
            pack2(e0 + o0 + bf0, e1 + o1 + bf1);
      }
    }
    __syncwarp();   // preds rows of this warp visible to all its lanes

    // GEMM2 + reward: z = hctx + preds @ WpT ; s = sum relu(z)*wr2
    float s[RW];
#pragma unroll
    for (int r = 0; r < RW; r++) s[r] = 0.f;

#pragma unroll
    for (int p = 0; p < 2; p++) {
      const int h0 = p * 64 + dl;
      u64 acc2[RW][2];
#pragma unroll
      for (int r = 0; r < RW; r++) { acc2[r][0] = 0ull; acc2[r][1] = 0ull; }

      for (int db = 0; db < D_; db += 4) {
        const int dp = db >> 1;
        ulonglong2 w0 = *reinterpret_cast<const ulonglong2*>(&WPH[(dp + 0) * WPH_STRIDE + h0]);
        ulonglong2 w1 = *reinterpret_cast<const ulonglong2*>(&WPH[(dp + 1) * WPH_STRIDE + h0]);
#pragma unroll
        for (int r = 0; r < RW; r++) {
          ulonglong2 x2 = *reinterpret_cast<const ulonglong2*>(&smf[OFF_PREDS + (r0 + r) * D_ + db]);
          ffma2(acc2[r][0], x2.x, w0.x);
          ffma2(acc2[r][1], x2.x, w0.y);
          ffma2(acc2[r][0], x2.y, w1.x);
          ffma2(acc2[r][1], x2.y, w1.y);
        }
      }
#pragma unroll
      for (int r = 0; r < RW; r++) {
        float hc0, hc1, e0, o0, e1, o1;
        unpack2(*reinterpret_cast<const u64*>(&smf[OFF_HCTX + (r0 + r) * H_ + h0]), hc0, hc1);
        unpack2(acc2[r][0], e0, o0);
        unpack2(acc2[r][1], e1, o1);
        float v0 = fmaxf(e0 + o0 + hc0, 0.f);
        float v1 = fmaxf(e1 + o1 + hc1, 0.f);
        s[r] = fmaf(v0, wr2v[p][0], s[r]);
        s[r] = fmaf(v1, wr2v[p][1], s[r]);
      }
    }

    // warp-reduce rewards (all lanes end with full sums)
#pragma unroll
    for (int off = 16; off >= 1; off >>= 1)
#pragma unroll
      for (int r = 0; r < RW; r++)
        s[r] += __shfl_xor_sync(0xffffffffu, s[r], off);

    // argmin + copy-on-improve (uniform across warp)
#pragma unroll
    for (int r = 0; r < RW; r++) {
      if (s[r] < bestr[r]) {   // strict < => first-min wins (matches argmin)
        bestr[r] = s[r];
        u64 pv = *reinterpret_cast<const u64*>(&smf[OFF_PREDS + (r0 + r) * D_ + dl]);
        *reinterpret_cast<u64*>(&out[(size_t)(b0g + r0 + r) * D_ + dl]) = pv;
      }
    }
  }
}

extern "C" void kernel_launch(void* const* d_in, const int* in_sizes, int n_in,
                              void* d_out, int out_size) {
  (void)in_sizes; (void)n_in; (void)out_size;
  const int*   x    = (const int*)d_in[0];
  const int*   y    = (const int*)d_in[1];
  const float* cemb = (const float*)d_in[2];
  const float* wemb = (const float*)d_in[3];
  const float* W1   = (const float*)d_in[4];
  const float* b1   = (const float*)d_in[5];
  const float* W2   = (const float*)d_in[6];
  const float* b2   = (const float*)d_in[7];
  const float* Wr1  = (const float*)d_in[8];
  const float* br1  = (const float*)d_in[9];
  const float* Wr2  = (const float*)d_in[10];
  float* out = (float*)d_out;

  cudaFuncSetAttribute(cmb_fused_kernel,
                       cudaFuncAttributeMaxDynamicSharedMemorySize,
                       SMEM_BYTES);

  cmb_precompute_kernel<<<A_, 256>>>(W1, b1, W2, b2);
  cmb_fused_kernel<<<B_ / TB, NT, SMEM_BYTES>>>(
      x, y, cemb, wemb, Wr1, br1, Wr2, out);
}

// round 7
// speedup vs baseline: 1.0367x; 1.0367x over previous
#include <cuda_runtime.h>
#include <cstdint>

namespace {

constexpr int B_ = 32768, A_ = 32, D_ = 64, H_ = 128, K_ = 128;
constexpr int TB = 128, NT2 = 256, NTILES = 66;
constexpr int ASTR = 132;                    // floats per padded row (528 B)
constexpr int PLANE = 64 * ASTR * 4;         // 33792 B : one B-tile tf32 plane
constexpr int TILE_BYTES = 2 * PLANE + 256;  // hi + lo + c2 = 67840 B

// K2 dynamic smem byte offsets
constexpr int OFF_AHI   = 0;                  // 128 x 132 f = 67584
constexpr int OFF_ALO   = 67584;
constexpr int OFF_B     = 135168;             // staged tile (hi, lo, c2) 67840
constexpr int OFF_C2    = OFF_B + 2 * PLANE;  // 202752 (inside staged tile)
constexpr int OFF_RED   = 203008;             // partial[2][128] f
constexpr int OFF_BESTR = 204032;             // float[128]
constexpr int OFF_ABEST = 204544;             // int[128]
constexpr int SMEM2     = 205056;

__device__ __forceinline__ uint32_t smem_u32(const void* p) {
  uint32_t a;
  asm("{ .reg .u64 t; cvta.to.shared.u64 t, %1; cvt.u32.u64 %0, t; }" : "=r"(a) : "l"(p));
  return a;
}
__device__ __forceinline__ uint32_t tf32f(float v) {
  uint32_t r;
  asm("cvt.rna.tf32.f32 %0, %1;" : "=r"(r) : "f"(v));
  return r;
}
__device__ __forceinline__ void ldsm4(uint32_t r[4], uint32_t addr) {
  asm volatile("ldmatrix.sync.aligned.m8n8.x4.shared.b16 {%0,%1,%2,%3}, [%4];"
               : "=r"(r[0]), "=r"(r[1]), "=r"(r[2]), "=r"(r[3]) : "r"(addr));
}
__device__ __forceinline__ void mma_tf32(float c[4], const uint32_t a[4],
                                         uint32_t b0, uint32_t b1) {
  asm volatile(
      "mma.sync.aligned.m16n8k8.row.col.f32.tf32.tf32.f32 "
      "{%0,%1,%2,%3}, {%4,%5,%6,%7}, {%8,%9}, {%0,%1,%2,%3};"
      : "+f"(c[0]), "+f"(c[1]), "+f"(c[2]), "+f"(c[3])
      : "r"(a[0]), "r"(a[1]), "r"(a[2]), "r"(a[3]), "r"(b0), "r"(b1));
}

}  // namespace

// -------- device scratch (no runtime alloc) --------
__device__ float g_weff[A_ * K_ * D_];   // [a][k][d] fp32
__device__ float g_beff[A_ * D_];        // [a][d]
__device__ __align__(16) unsigned char g_btiles[(size_t)NTILES * TILE_BYTES];
__device__ int g_bcnt[A_];
__device__ int g_bucket[A_ * B_];

// ---------------------------------------------------------------------------
// K1a: Weff[a][k][d] = sum_h W2[a][d][h]*W1[a][h][k];  beff
// ---------------------------------------------------------------------------
__global__ void __launch_bounds__(256)
k1a_weff(const float* __restrict__ W1, const float* __restrict__ b1,
         const float* __restrict__ W2, const float* __restrict__ b2) {
  __shared__ float w1s[H_][K_];
  __shared__ float w2s[D_][H_];
  const int a = blockIdx.x, tid = threadIdx.x;
  const float* W1a = W1 + (size_t)a * H_ * K_;
  const float* W2a = W2 + (size_t)a * D_ * H_;
  for (int i = tid; i < H_ * K_ / 4; i += 256)
    reinterpret_cast<float4*>(&w1s[0][0])[i] = reinterpret_cast<const float4*>(W1a)[i];
  for (int i = tid; i < D_ * H_ / 4; i += 256)
    reinterpret_cast<float4*>(&w2s[0][0])[i] = reinterpret_cast<const float4*>(W2a)[i];
  __syncthreads();

  const int k0 = (tid & 31) * 4, d0 = (tid >> 5) * 8;
  float acc[4][8];
#pragma unroll
  for (int i = 0; i < 4; i++)
#pragma unroll
    for (int j = 0; j < 8; j++) acc[i][j] = 0.f;
  for (int h = 0; h < H_; h++) {
    float4 w1v = *reinterpret_cast<const float4*>(&w1s[h][k0]);
    float w1x[4] = {w1v.x, w1v.y, w1v.z, w1v.w};
#pragma unroll
    for (int j = 0; j < 8; j++) {
      float w2v = w2s[d0 + j][h];
#pragma unroll
      for (int i = 0; i < 4; i++) acc[i][j] = fmaf(w2v, w1x[i], acc[i][j]);
    }
  }
  float* dst = g_weff + (size_t)a * K_ * D_;
#pragma unroll
  for (int i = 0; i < 4; i++)
#pragma unroll
    for (int j = 0; j < 8; j++) dst[(k0 + i) * D_ + d0 + j] = acc[i][j];

  if (tid < D_) {
    float s = b2[a * D_ + tid];
    for (int h = 0; h < H_; h++) s = fmaf(w2s[tid][h], b1[a * H_ + h], s);
    g_beff[a * D_ + tid] = s;
  }
}

// ---------------------------------------------------------------------------
// K1b: build B tiles (tf32 hi/lo planes [n][k] stride 132, + c2[64]).
//  t<2 : B[n][k]=Wr1[t*64+n][k],            c2[n]=br1[t*64+n]
//  t>=2: B[n][k]=sum_d Weff[a][k][d]*Wp[h][d], h=hf*64+n; c2[n]=beff.Wp[h]
// Also zeroes bucket counters (graph-replay safe).
// ---------------------------------------------------------------------------
__global__ void __launch_bounds__(256)
k1b_btiles(const float* __restrict__ Wr1, const float* __restrict__ br1) {
  __shared__ float weffs[K_ * D_];   // 32 KB
  __shared__ float wps[64 * D_];     // 16 KB
  const int t = blockIdx.x, tid = threadIdx.x;
  unsigned char* base = g_btiles + (size_t)t * TILE_BYTES;
  uint32_t* phi = reinterpret_cast<uint32_t*>(base);
  uint32_t* plo = reinterpret_cast<uint32_t*>(base + PLANE);
  float* c2 = reinterpret_cast<float*>(base + 2 * PLANE);

  if (t == 0 && tid < A_) g_bcnt[tid] = 0;

  const int k = tid >> 1, n0 = (tid & 1) * 32;

  if (t < 2) {
    for (int n = n0; n < n0 + 32; n++) {
      float v = Wr1[(t * 64 + n) * 192 + k];
      uint32_t hh = tf32f(v);
      uint32_t ll = tf32f(v - __uint_as_float(hh));
      phi[n * ASTR + k] = hh;
      plo[n * ASTR + k] = ll;
    }
    if (tid < 64) c2[tid] = br1[t * 64 + tid];
    return;
  }

  const int a = (t - 2) >> 1;
  const int hf = (t - 2) & 1;
  for (int i = tid; i < K_ * D_ / 4; i += 256)
    reinterpret_cast<float4*>(weffs)[i] =
        reinterpret_cast<const float4*>(g_weff + (size_t)a * K_ * D_)[i];
  for (int i = tid; i < 64 * 64 / 4; i += 256) {
    int n = i >> 4, q = i & 15;
    *reinterpret_cast<float4*>(&wps[n * 64 + q * 4]) =
        *reinterpret_cast<const float4*>(&Wr1[(hf * 64 + n) * 192 + 128 + q * 4]);
  }
  __syncthreads();

  for (int n = n0; n < n0 + 32; n++) {
    float s = 0.f;
#pragma unroll 4
    for (int d = 0; d < D_; d++) s = fmaf(weffs[k * D_ + d], wps[n * 64 + d], s);
    uint32_t hh = tf32f(s);
    uint32_t ll = tf32f(s - __uint_as_float(hh));
    phi[n * ASTR + k] = hh;
    plo[n * ASTR + k] = ll;
  }
  if (tid < 64) {
    float s = 0.f;
    for (int d = 0; d < D_; d++) s = fmaf(g_beff[a * D_ + d], wps[tid * 64 + d], s);
    c2[tid] = s;
  }
}

// ---------------------------------------------------------------------------
// K2: 3xTF32 mma.sync GEMM over 66 tiles + reward/argmin epilogue.
// Warp tile m32 x n32 (8 warps: 4 m-stripes x 2 n-halves).
// ---------------------------------------------------------------------------
__global__ void __launch_bounds__(NT2, 1)
k2_gemm(const int* __restrict__ x, const int* __restrict__ y,
        const float* __restrict__ cemb, const float* __restrict__ wemb,
        const float* __restrict__ Wr2, float* __restrict__ out) {
  extern __shared__ char sm[];
  float* smf = reinterpret_cast<float*>(sm);
  const uint32_t smb = smem_u32(sm);
  const int tid = threadIdx.x, wid = tid >> 5, lid = tid & 31;
  const int ms = wid >> 1, nh = wid & 1;
  const int tq = lid & 3, g = lid >> 2;
  const int b0g = blockIdx.x * TB;

  // ---- prologue: ctx gather + tf32 split into A planes; wemb copy; init ----
  {
    int row = tid >> 1, halfk = tid & 1;
    int gb = b0g + row;
    int xi = x[gb * 2 + halfk];
    const float4* src = reinterpret_cast<const float4*>(cemb + (size_t)xi * 64);
    uint32_t* ahi = reinterpret_cast<uint32_t*>(sm + OFF_AHI);
    uint32_t* alo = reinterpret_cast<uint32_t*>(sm + OFF_ALO);
#pragma unroll
    for (int q = 0; q < 16; q++) {
      float4 v = src[q];
      float vv[4] = {v.x, v.y, v.z, v.w};
#pragma unroll
      for (int j = 0; j < 4; j++) {
        int k = halfk * 64 + q * 4 + j;
        uint32_t hh = tf32f(vv[j]);
        uint32_t ll = tf32f(vv[j] - __uint_as_float(hh));
        ahi[row * ASTR + k] = hh;
        alo[row * ASTR + k] = ll;
      }
    }
    int yy = y[gb];
#pragma unroll
    for (int q = 0; q < 8; q++) {
      int d = halfk * 32 + q * 4;
      *reinterpret_cast<float4*>(&out[(size_t)B_ * 64 + (size_t)gb * 64 + d]) =
          *reinterpret_cast<const float4*>(wemb + (size_t)yy * 64 + d);
    }
  }
  if (tid < 128) {
    smf[OFF_BESTR / 4 + tid] = 3.0e38f;
    reinterpret_cast<int*>(sm + OFF_ABEST)[tid] = 0;
  }

  // wr2 registers at this lane's column coords
  float wr2r[2][4][2];
#pragma unroll
  for (int hf = 0; hf < 2; hf++)
#pragma unroll
    for (int nt = 0; nt < 4; nt++) {
      int h = hf * 64 + nh * 32 + nt * 8 + 2 * tq;
      wr2r[hf][nt][0] = Wr2[h];
      wr2r[hf][nt][1] = Wr2[h + 1];
    }

  const uint32_t laneoff = (uint32_t)((lid & 15) * 528 + (lid >> 4) * 16);
  float hctx[2][2][4][4];
  float sacc[4] = {0.f, 0.f, 0.f, 0.f};

  for (int t = 0; t < NTILES; t++) {
    __syncthreads();   // prior tile fully consumed
    {
      const uint4* s4 = reinterpret_cast<const uint4*>(g_btiles + (size_t)t * TILE_BYTES);
      uint4* d4 = reinterpret_cast<uint4*>(sm + OFF_B);
      for (int i = tid; i < TILE_BYTES / 16; i += NT2) d4[i] = s4[i];
    }
    __syncthreads();

    float acc[2][4][4];
#pragma unroll
    for (int mt = 0; mt < 2; mt++)
#pragma unroll
      for (int nt = 0; nt < 4; nt++)
#pragma unroll
        for (int c = 0; c < 4; c++) acc[mt][nt][c] = 0.f;

#pragma unroll 1
    for (int term = 0; term < 3; term++) {
      const uint32_t ab = smb + (term == 2 ? OFF_ALO : OFF_AHI) + ms * 16896 + laneoff;
      const uint32_t bb = smb + OFF_B + (term == 1 ? PLANE : 0) + nh * 16896 + laneoff;
#pragma unroll 4
      for (int ks = 0; ks < 16; ks++) {
        uint32_t af[2][4], bf[2][4];
        ldsm4(af[0], ab + ks * 32);
        ldsm4(af[1], ab + 8448 + ks * 32);
        ldsm4(bf[0], bb + ks * 32);
        ldsm4(bf[1], bb + 8448 + ks * 32);
#pragma unroll
        for (int mt = 0; mt < 2; mt++)
#pragma unroll
          for (int nt = 0; nt < 4; nt++) {
            int j = nt >> 1, e = nt & 1;
            mma_tf32(acc[mt][nt], af[mt], bf[j][e], bf[j][2 + e]);
          }
      }
    }

    // c2 at this lane's cols
    float c2v[4][2];
    const float* c2p = reinterpret_cast<const float*>(sm + OFF_C2);
#pragma unroll
    for (int nt = 0; nt < 4; nt++) {
      c2v[nt][0] = c2p[nh * 32 + nt * 8 + 2 * tq];
      c2v[nt][1] = c2p[nh * 32 + nt * 8 + 2 * tq + 1];
    }

    if (t < 2) {
#pragma unroll
      for (int mt = 0; mt < 2; mt++)
#pragma unroll
        for (int nt = 0; nt < 4; nt++)
#pragma unroll
          for (int c = 0; c < 4; c++)
            hctx[t][mt][nt][c] = acc[mt][nt][c] + c2v[nt][c & 1];
    } else {
      const int hf = (t - 2) & 1;
      const int act = (t - 2) >> 1;
      float s[4];
#pragma unroll
      for (int mt = 0; mt < 2; mt++)
#pragma unroll
        for (int r = 0; r < 2; r++) {
          float v = 0.f;
#pragma unroll
          for (int nt = 0; nt < 4; nt++) {
            float z0 = acc[mt][nt][r * 2 + 0] + hctx[hf][mt][nt][r * 2 + 0] + c2v[nt][0];
            float z1 = acc[mt][nt][r * 2 + 1] + hctx[hf][mt][nt][r * 2 + 1] + c2v[nt][1];
            v = fmaf(fmaxf(z0, 0.f), wr2r[hf][nt][0], v);
            v = fmaf(fmaxf(z1, 0.f), wr2r[hf][nt][1], v);
          }
          s[mt * 2 + r] = v;
        }
      if (hf == 0) {
#pragma unroll
        for (int i = 0; i < 4; i++) sacc[i] = s[i];
      } else {
#pragma unroll
        for (int i = 0; i < 4; i++) s[i] += sacc[i];
#pragma unroll
        for (int i = 0; i < 4; i++) {
          s[i] += __shfl_xor_sync(0xffffffffu, s[i], 1);
          s[i] += __shfl_xor_sync(0xffffffffu, s[i], 2);
        }
        if (tq == 0) {
#pragma unroll
          for (int i = 0; i < 4; i++) {
            int row = ms * 32 + (i >> 1) * 16 + (i & 1) * 8 + g;
            smf[OFF_RED / 4 + nh * 128 + row] = s[i];
          }
        }
        __syncthreads();
        if (tid < 128) {
          float tot = smf[OFF_RED / 4 + tid] + smf[OFF_RED / 4 + 128 + tid];
          if (tot < smf[OFF_BESTR / 4 + tid]) {   // strict < => first-min wins
            smf[OFF_BESTR / 4 + tid] = tot;
            reinterpret_cast<int*>(sm + OFF_ABEST)[tid] = act;
          }
        }
      }
    }
  }

  __syncthreads();
  if (tid < 128) {
    int ab = reinterpret_cast<int*>(sm + OFF_ABEST)[tid];
    int slot = atomicAdd(&g_bcnt[ab], 1);
    g_bucket[ab * B_ + slot] = b0g + tid;
  }
}

// ---------------------------------------------------------------------------
// K3: winner preds (exact fp32), bucketed by action.
// ---------------------------------------------------------------------------
__global__ void __launch_bounds__(256)
k3_preds(const int* __restrict__ x, const float* __restrict__ cemb,
         float* __restrict__ out) {
  __shared__ float weffs[K_ * D_];
  __shared__ float ctxb[8][K_];
  const int a = blockIdx.x >> 3;
  const int chunk = blockIdx.x & 7;
  const int tid = threadIdx.x, wid = tid >> 5, lid = tid & 31;

  for (int i = tid; i < K_ * D_ / 4; i += 256)
    reinterpret_cast<float4*>(weffs)[i] =
        reinterpret_cast<const float4*>(g_weff + (size_t)a * K_ * D_)[i];
  __syncthreads();

  const int cnt = g_bcnt[a];
  const float bf0 = g_beff[a * D_ + 2 * lid];
  const float bf1 = g_beff[a * D_ + 2 * lid + 1];

  for (int ii = wid;; ii += 8) {
    int i = chunk + 8 * ii;
    if (i >= cnt) break;
    int b = g_bucket[a * B_ + i];
    {
      int k0 = lid * 4;
      int xi = x[2 * b + (lid >> 4)];
      float4 v = *reinterpret_cast<const float4*>(cemb + (size_t)xi * 64 + (k0 & 63));
      *reinterpret_cast<float4*>(&ctxb[wid][k0]) = v;
    }
    __syncwarp();
    float s0 = bf0, s1 = bf1;
#pragma unroll 4
    for (int k = 0; k < K_; k++) {
      float c = ctxb[wid][k];
      s0 = fmaf(c, weffs[k * D_ + 2 * lid], s0);
      s1 = fmaf(c, weffs[k * D_ + 2 * lid + 1], s1);
    }
    *reinterpret_cast<float2*>(&out[(size_t)b * 64 + 2 * lid]) = make_float2(s0, s1);
    __syncwarp();
  }
}

extern "C" void kernel_launch(void* const* d_in, const int* in_sizes, int n_in,
                              void* d_out, int out_size) {
  (void)in_sizes; (void)n_in; (void)out_size;
  const int*   x    = (const int*)d_in[0];
  const int*   y    = (const int*)d_in[1];
  const float* cemb = (const float*)d_in[2];
  const float* wemb = (const float*)d_in[3];
  const float* W1   = (const float*)d_in[4];
  const float* b1   = (const float*)d_in[5];
  const float* W2   = (const float*)d_in[6];
  const float* b2   = (const float*)d_in[7];
  const float* Wr1  = (const float*)d_in[8];
  const float* br1  = (const float*)d_in[9];
  const float* Wr2  = (const float*)d_in[10];
  float* out = (float*)d_out;

  cudaFuncSetAttribute(k2_gemm, cudaFuncAttributeMaxDynamicSharedMemorySize, SMEM2);

  k1a_weff<<<A_, 256>>>(W1, b1, W2, b2);
  k1b_btiles<<<NTILES, 256>>>(Wr1, br1);
  k2_gemm<<<B_ / TB, NT2, SMEM2>>>(x, y, cemb, wemb, Wr2, out);
  k3_preds<<<A_ * 8, 256>>>(x, cemb, out);
}